// round 7
// baseline (speedup 1.0000x reference)
#include <cuda_runtime.h>
#include <stdint.h>

#define BN_EPS 1e-5f

namespace {
constexpr int Nn = 64, C = 256, H = 56, W = 56;
constexpr int HP = H + 2, WPAD = W + 2;
constexpr int WORDS = C / 32;
constexpr int KW = 9 * WORDS;                    // 72
constexpr int TH = 8;
constexpr int ROWSTR = 34;
constexpr int PLANE = (TH + 2) * ROWSTR;         // 340
constexpr long long PIXWORDS = (long long)Nn * HP * WPAD * WORDS;
}

__device__ uint32_t g_s1[Nn * HP * WPAD * WORDS];
__device__ uint32_t g_s2[Nn * HP * WPAD * WORDS];
__device__ uint32_t g_z2[Nn * HP * WPAD * WORDS];
__device__ uint32_t g_wb1[C * KW];
__device__ uint32_t g_wb2[C * KW];
__device__ int g_D0[9 * C];                      // border-case correction for conv1
__device__ float g_sc1[C], g_sh1[C], g_sc2[C], g_sh2[C];

// Full adder: 3 words -> sum (weight 1) + carry (weight 2). One LOP3 each.
__device__ __forceinline__ void fa(uint32_t a, uint32_t b, uint32_t c,
                                   uint32_t& s, uint32_t& cy) {
    s = a ^ b ^ c;
    cy = (a & b) | (c & (a | b));
}
__device__ __forceinline__ void madacc2(int& a, int p) {  // a += 2*p (fma pipe)
    asm("mad.lo.s32 %0, %1, 2, %0;" : "+r"(a) : "r"(p));
}
__device__ __forceinline__ void madacc4(int& a, int p) {  // a += 4*p (fma pipe)
    asm("mad.lo.s32 %0, %1, 4, %0;" : "+r"(a) : "r"(p));
}
__device__ __forceinline__ int madn2(int acc, int d0) {   // d0 - 2*acc (fma pipe)
    int r;
    asm("mad.lo.s32 %0, %1, -2, %2;" : "=r"(r) : "r"(acc), "r"(d0));
    return r;
}

__global__ void k_zero() {
    long long stride = (long long)gridDim.x * blockDim.x;
    for (long long i = blockIdx.x * (long long)blockDim.x + threadIdx.x;
         i < PIXWORDS; i += stride) {
        g_s1[i] = 0u;   // conv1 padding: sign bits 0 (corrected exactly via D0)
        g_z2[i] = 0u;   // conv2 padding: nz = 0
    }
}

__global__ void k_pack_x(const float* __restrict__ x) {
    const int h = blockIdx.x, n = blockIdx.y;
    const int w = threadIdx.x, wd = threadIdx.y;
    const float* xp = x + (((long long)n * C + wd * 32) * H + h) * W + w;
    uint32_t s = 0;
#pragma unroll
    for (int ci = 0; ci < 32; ci++)
        s |= (xp[(long long)ci * (H * W)] > 0.f ? 1u : 0u) << ci;
    g_s1[(((long long)n * HP + (h + 1)) * WPAD + (w + 1)) * WORDS + wd] = s;
}

__global__ void k_pack_w(const float* __restrict__ w, int which) {
    uint32_t* __restrict__ outw = which ? g_wb2 : g_wb1;
    const int co = blockIdx.x, wd = threadIdx.x, tap = threadIdx.y;
    uint32_t s = 0;
#pragma unroll
    for (int ci = 0; ci < 32; ci++)
        s |= (w[(((long long)co * C) + wd * 32 + ci) * 9 + tap] > 0.f ? 1u : 0u) << ci;
    outw[co * KW + tap * WORDS + wd] = s;
}

// For interior pixels with x in {-1,+1}^256: dot = 2304 - 2*sum_taps popc(xs^w).
// At borders, invalid taps read xs=0 so popc(0^w)=popc(w); their true
// contribution is 0. So dot = 256*V - 2*(acc - sum_{invalid} popc(w))
//                      = (256*V + 2*P) - 2*acc = D0[case] - 2*acc. Exact ints.
__global__ void k_prep_d0() {
    const int co = threadIdx.x;
    int pc[9];
#pragma unroll
    for (int t = 0; t < 9; t++) {
        int s = 0;
#pragma unroll
        for (int wd = 0; wd < WORDS; wd++) s += __popc(g_wb1[co * KW + t * WORDS + wd]);
        pc[t] = s;
    }
#pragma unroll
    for (int cs = 0; cs < 9; cs++) {
        int hc = cs / 3, wc = cs % 3, V = 0, P = 0;
#pragma unroll
        for (int t = 0; t < 9; t++) {
            int dh = t / 3, dw = t % 3;
            bool inval = (dh == 0 && hc == 0) || (dh == 2 && hc == 2) ||
                         (dw == 0 && wc == 0) || (dw == 2 && wc == 2);
            if (inval) P += pc[t]; else V++;
        }
        g_D0[cs * C + co] = 256 * V + 2 * P;
    }
}

__global__ void k_prep_bn(const float* __restrict__ g, const float* __restrict__ b,
                          const float* __restrict__ m, const float* __restrict__ v,
                          int which) {
    int c = threadIdx.x;
    float sc = g[c] * rsqrtf(v[c] + BN_EPS);
    float sh = b[c] - m[c] * sc;
    if (which) { g_sc2[c] = sc; g_sh2[c] = sh; }
    else       { g_sc1[c] = sc; g_sh1[c] = sh; }
}

// ---- conv1: sign-only (no nz plane); borders via D0 table ----
__global__ __launch_bounds__(256, 2) void k_bconv1() {
    __shared__ uint32_t xs[WORDS * PLANE];
    __shared__ int d0s[9 * C];
    __shared__ float scs[C], shs[C];

    const int chunk = blockIdx.x, h0 = blockIdx.y * TH, n = blockIdx.z;
    const int tid = threadIdx.x, w0 = chunk * 32;

    for (int i = tid; i < WORDS * PLANE; i += 256) {
        int wd = i & 7, c = (i >> 3) % ROWSTR, r = (i >> 3) / ROWSTR;
        int col = w0 + c;
        uint32_t s = 0;
        if (col < WPAD)
            s = g_s1[(((long long)n * HP + (h0 + r)) * WPAD + col) * WORDS + wd];
        xs[wd * PLANE + r * ROWSTR + c] = s;
    }
    for (int i = tid; i < 9 * C; i += 256) d0s[i] = g_D0[i];
    if (tid < C) { scs[tid] = g_sc1[tid]; shs[tid] = g_sh1[tid]; }
    __syncthreads();

    const int lane = tid & 31, wid = tid >> 5;
    const int ow = w0 + lane;
    const bool act = (ow < W);
    const int wc = (ow == 0) ? 0 : (ow == W - 1) ? 2 : 1;

    uint32_t osig[TH], onz[TH];
#pragma unroll
    for (int r = 0; r < TH; r++) { osig[r] = 0u; onz[r] = 0u; }

    for (int j0 = 0; j0 < 32; j0 += 4) {
        int acc[4][TH];
#pragma unroll
        for (int jj = 0; jj < 4; jj++)
#pragma unroll
            for (int r = 0; r < TH; r++) acc[jj][r] = 0;

        const uint32_t* wp = g_wb1 + (wid * 32 + j0) * KW;
        for (int g = 0; g < 8; g++) {
            uint32_t wk[4][9];
#pragma unroll
            for (int c4 = 0; c4 < 4; c4++)
#pragma unroll
                for (int t = 0; t < 9; t++) wk[c4][t] = __ldg(wp + c4 * KW + g * 9 + t);
            int off[9];
#pragma unroll
            for (int q = 0; q < 9; q++) {
                int k = g * 9 + q;
                int wd = k & 7, tap = k >> 3;
                off[q] = wd * PLANE + (tap / 3) * ROWSTR + (tap % 3) + lane;
            }
#pragma unroll
            for (int r = 0; r < TH; r++) {
                uint32_t sA[4][3], cA[4][3];
#pragma unroll
                for (int t3 = 0; t3 < 3; t3++) {
                    uint32_t x0 = xs[off[t3 * 3 + 0] + r * ROWSTR];
                    uint32_t x1 = xs[off[t3 * 3 + 1] + r * ROWSTR];
                    uint32_t x2 = xs[off[t3 * 3 + 2] + r * ROWSTR];
#pragma unroll
                    for (int c4 = 0; c4 < 4; c4++)
                        fa(x0 ^ wk[c4][t3 * 3 + 0], x1 ^ wk[c4][t3 * 3 + 1],
                           x2 ^ wk[c4][t3 * 3 + 2], sA[c4][t3], cA[c4][t3]);
                }
#pragma unroll
                for (int c4 = 0; c4 < 4; c4++) {
                    uint32_t S, C2, S2, C4w;
                    fa(sA[c4][0], sA[c4][1], sA[c4][2], S, C2);
                    fa(cA[c4][0], cA[c4][1], cA[c4][2], S2, C4w);
                    int a = acc[c4][r];
                    a += __popc(S);
                    madacc2(a, __popc(C2) + __popc(S2));
                    madacc4(a, __popc(C4w));
                    acc[c4][r] = a;
                }
            }
        }
#pragma unroll
        for (int jj = 0; jj < 4; jj++) {
            const int co = wid * 32 + j0 + jj;
            const float sc = scs[co], sh = shs[co];
#pragma unroll
            for (int r = 0; r < TH; r++) {
                const int h = h0 + r;
                const int hc = (h == 0) ? 0 : (h == H - 1) ? 2 : 1;
                const int dot = madn2(acc[jj][r], d0s[(hc * 3 + wc) * C + co]);
                const float t = fmaf((float)dot, sc, sh);
                osig[r] |= (t > 0.f ? 1u : 0u) << (j0 + jj);
                onz[r] |= (t != 0.f ? 1u : 0u) << (j0 + jj);
            }
        }
    }

    if (act) {
#pragma unroll
        for (int r = 0; r < TH; r++) {
            long long gi =
                (((long long)n * HP + (h0 + r + 1)) * WPAD + (ow + 1)) * WORDS + wid;
            g_s2[gi] = osig[r];
            g_z2[gi] = onz[r];
        }
    }
}

// ---- conv2: data-dependent zeros -> keep nz plane + base loop ----
__global__ __launch_bounds__(256, 2) void k_bconv2(const float* __restrict__ xres,
                                                   float* __restrict__ out) {
    __shared__ uint32_t xs[WORDS * PLANE];
    __shared__ uint32_t xz[WORDS * PLANE];
    __shared__ float scs[C], shs[C];

    const int chunk = blockIdx.x, h0 = blockIdx.y * TH, n = blockIdx.z;
    const int tid = threadIdx.x, w0 = chunk * 32;

    for (int i = tid; i < WORDS * PLANE; i += 256) {
        int wd = i & 7, c = (i >> 3) % ROWSTR, r = (i >> 3) / ROWSTR;
        int col = w0 + c;
        uint32_t s = 0, z = 0;
        if (col < WPAD) {
            long long gi = (((long long)n * HP + (h0 + r)) * WPAD + col) * WORDS + wd;
            s = g_s2[gi];
            z = g_z2[gi];
        }
        xs[wd * PLANE + r * ROWSTR + c] = s;
        xz[wd * PLANE + r * ROWSTR + c] = z;
    }
    if (tid < C) { scs[tid] = g_sc2[tid]; shs[tid] = g_sh2[tid]; }
    __syncthreads();

    const int lane = tid & 31, wid = tid >> 5;
    const int ow = w0 + lane;
    const bool act = (ow < W);

    int base[TH];
#pragma unroll
    for (int r = 0; r < TH; r++) base[r] = 0;
    for (int g = 0; g < 8; g++) {
        int off[9];
#pragma unroll
        for (int q = 0; q < 9; q++) {
            int k = g * 9 + q;
            int wd = k & 7, tap = k >> 3;
            off[q] = wd * PLANE + (tap / 3) * ROWSTR + (tap % 3) + lane;
        }
#pragma unroll
        for (int r = 0; r < TH; r++) {
            uint32_t s0, c0, s1, c1, s2, c2, S, C2, S2, C4;
            fa(xz[off[0] + r * ROWSTR], xz[off[1] + r * ROWSTR], xz[off[2] + r * ROWSTR], s0, c0);
            fa(xz[off[3] + r * ROWSTR], xz[off[4] + r * ROWSTR], xz[off[5] + r * ROWSTR], s1, c1);
            fa(xz[off[6] + r * ROWSTR], xz[off[7] + r * ROWSTR], xz[off[8] + r * ROWSTR], s2, c2);
            fa(s0, s1, s2, S, C2);
            fa(c0, c1, c2, S2, C4);
            int a = base[r];
            a += __popc(S);
            madacc2(a, __popc(C2) + __popc(S2));
            madacc4(a, __popc(C4));
            base[r] = a;
        }
    }

    for (int j0 = 0; j0 < 32; j0 += 4) {
        int acc[4][TH];
#pragma unroll
        for (int jj = 0; jj < 4; jj++)
#pragma unroll
            for (int r = 0; r < TH; r++) acc[jj][r] = 0;

        const uint32_t* wp = g_wb2 + (wid * 32 + j0) * KW;
        for (int g = 0; g < 8; g++) {
            uint32_t wk[4][9];
#pragma unroll
            for (int c4 = 0; c4 < 4; c4++)
#pragma unroll
                for (int t = 0; t < 9; t++) wk[c4][t] = __ldg(wp + c4 * KW + g * 9 + t);
            int off[9];
#pragma unroll
            for (int q = 0; q < 9; q++) {
                int k = g * 9 + q;
                int wd = k & 7, tap = k >> 3;
                off[q] = wd * PLANE + (tap / 3) * ROWSTR + (tap % 3) + lane;
            }
#pragma unroll
            for (int r = 0; r < TH; r++) {
                uint32_t sA[4][3], cA[4][3];
#pragma unroll
                for (int t3 = 0; t3 < 3; t3++) {
                    uint32_t sx0 = xs[off[t3 * 3 + 0] + r * ROWSTR];
                    uint32_t zx0 = xz[off[t3 * 3 + 0] + r * ROWSTR];
                    uint32_t sx1 = xs[off[t3 * 3 + 1] + r * ROWSTR];
                    uint32_t zx1 = xz[off[t3 * 3 + 1] + r * ROWSTR];
                    uint32_t sx2 = xs[off[t3 * 3 + 2] + r * ROWSTR];
                    uint32_t zx2 = xz[off[t3 * 3 + 2] + r * ROWSTR];
#pragma unroll
                    for (int c4 = 0; c4 < 4; c4++)
                        fa(zx0 & (sx0 ^ wk[c4][t3 * 3 + 0]),
                           zx1 & (sx1 ^ wk[c4][t3 * 3 + 1]),
                           zx2 & (sx2 ^ wk[c4][t3 * 3 + 2]),
                           sA[c4][t3], cA[c4][t3]);
                }
#pragma unroll
                for (int c4 = 0; c4 < 4; c4++) {
                    uint32_t S, C2, S2, C4w;
                    fa(sA[c4][0], sA[c4][1], sA[c4][2], S, C2);
                    fa(cA[c4][0], cA[c4][1], cA[c4][2], S2, C4w);
                    int a = acc[c4][r];
                    a += __popc(S);
                    madacc2(a, __popc(C2) + __popc(S2));
                    madacc4(a, __popc(C4w));
                    acc[c4][r] = a;
                }
            }
        }
#pragma unroll
        for (int jj = 0; jj < 4; jj++) {
            const int co = wid * 32 + j0 + jj;
            const float sc = scs[co], sh = shs[co];
            if (act) {
#pragma unroll
                for (int r = 0; r < TH; r++) {
                    const int dot = madn2(acc[jj][r], base[r]);
                    const float t = fmaf((float)dot, sc, sh);
                    long long oi = (((long long)n * C + co) * H + (h0 + r)) * W + ow;
                    float v = t + xres[oi];
                    out[oi] = fminf(1.f, fmaxf(-1.f, v));
                }
            }
        }
    }
}

extern "C" void kernel_launch(void* const* d_in, const int* in_sizes, int n_in,
                              void* d_out, int out_size) {
    (void)in_sizes; (void)n_in; (void)out_size;
    const float* x = (const float*)d_in[0];
    const float* w1 = (const float*)d_in[1];
    const float* g1 = (const float*)d_in[2];
    const float* b1 = (const float*)d_in[3];
    const float* m1 = (const float*)d_in[4];
    const float* v1 = (const float*)d_in[5];
    const float* w2 = (const float*)d_in[6];
    const float* g2 = (const float*)d_in[7];
    const float* b2 = (const float*)d_in[8];
    const float* m2 = (const float*)d_in[9];
    const float* v2 = (const float*)d_in[10];
    float* out = (float*)d_out;

    k_zero<<<1024, 256>>>();
    k_pack_x<<<dim3(H, Nn), dim3(W, WORDS)>>>(x);
    k_pack_w<<<C, dim3(WORDS, 9)>>>(w1, 0);
    k_pack_w<<<C, dim3(WORDS, 9)>>>(w2, 1);
    k_prep_d0<<<1, C>>>();
    k_prep_bn<<<1, C>>>(g1, b1, m1, v1, 0);
    k_prep_bn<<<1, C>>>(g2, b2, m2, v2, 1);

    dim3 grid(2, H / TH, Nn);
    k_bconv1<<<grid, 256>>>();
    k_bconv2<<<grid, 256>>>(x, out);
}